// round 4
// baseline (speedup 1.0000x reference)
#include <cuda_runtime.h>

#define N_NODES 50000
#define N_EDGES 800000
#define N_FEAT  500
#define N_HID   256
#define DCAT    512   // fused hidden width (2 branches x 256)
#define N_CLASS 10

// ---------------- device scratch (static; no allocations allowed) -------------
__device__ int   g_is64;                 // 1 if edge_index is int64, 0 if int32
__device__ int   g_counts[N_NODES];
__device__ int   g_row_start[N_NODES + 1];
__device__ int   g_cursor[N_NODES];
__device__ int   g_col[N_EDGES];
__device__ float g_w[N_EDGES];
__device__ float g_y[(size_t)N_NODES * DCAT];   // x@W1cat + b1cat
__device__ float g_g[(size_t)N_NODES * DCAT];   // relu(spmm(y))
__device__ float g_z[(size_t)N_NODES * 20];     // [z1(10) | z2(10)] per node

// ---------------- dtype detect ------------------------------------------------
// int64 little-endian with 0 <= v < 2^31  ->  every odd int32 word is 0.
// int32 node ids at odd positions are ~never all zero over 64 samples.
__global__ void k_detect(const int* __restrict__ ei32) {
    if (threadIdx.x == 0) {
        int odd_nonzero = 0;
        for (int i = 0; i < 64; i++)
            odd_nonzero |= ei32[2 * i + 1];
        g_is64 = (odd_nonzero == 0) ? 1 : 0;
    }
}

__device__ __forceinline__ int edge_row(const int* ei32, int e, int is64) {
    return is64 ? ei32[2 * e] : ei32[e];
}
__device__ __forceinline__ int edge_col(const int* ei32, int e, int is64) {
    return is64 ? ei32[2 * (N_EDGES + e)] : ei32[N_EDGES + e];
}

// ---------------- CSR build ---------------------------------------------------
__global__ void k_zero() {
    int i = blockIdx.x * blockDim.x + threadIdx.x;
    if (i < N_NODES) { g_counts[i] = 0; g_cursor[i] = 0; }
}

__global__ void k_hist(const int* __restrict__ ei32) {
    int e = blockIdx.x * blockDim.x + threadIdx.x;
    if (e < N_EDGES) {
        int r = edge_row(ei32, e, g_is64);
        if ((unsigned)r < N_NODES) atomicAdd(&g_counts[r], 1);
    }
}

// single-block exclusive scan over 50000 counts
__global__ void k_scan() {
    __shared__ int sm[1024];
    __shared__ int carry;
    if (threadIdx.x == 0) carry = 0;
    __syncthreads();
    for (int base = 0; base < N_NODES; base += 1024) {
        int i = base + threadIdx.x;
        int v = (i < N_NODES) ? g_counts[i] : 0;
        sm[threadIdx.x] = v;
        __syncthreads();
        for (int off = 1; off < 1024; off <<= 1) {
            int t = (threadIdx.x >= off) ? sm[threadIdx.x - off] : 0;
            __syncthreads();
            sm[threadIdx.x] += t;
            __syncthreads();
        }
        int c = carry;
        if (i < N_NODES) g_row_start[i] = c + sm[threadIdx.x] - v;
        int tot = sm[1023];
        __syncthreads();
        if (threadIdx.x == 0) carry = c + tot;
        __syncthreads();
    }
    if (threadIdx.x == 0) g_row_start[N_NODES] = carry;
}

__global__ void k_scatter(const int* __restrict__ ei32,
                          const float* __restrict__ ew) {
    int e = blockIdx.x * blockDim.x + threadIdx.x;
    if (e < N_EDGES) {
        int is64 = g_is64;
        int r = edge_row(ei32, e, is64);
        int c = edge_col(ei32, e, is64);
        if ((unsigned)r < N_NODES && (unsigned)c < N_NODES) {
            int p = g_row_start[r] + atomicAdd(&g_cursor[r], 1);
            g_col[p] = c;
            g_w[p]   = ew[e];
        }
    }
}

// ---------------- GEMM1: y[50000,512] = x[50000,500] @ W1cat + b1cat ----------
__global__ void __launch_bounds__(256) k_gemm1(
    const float* __restrict__ x,
    const float* __restrict__ W1a, const float* __restrict__ b1a,
    const float* __restrict__ W1b, const float* __restrict__ b1b)
{
    __shared__ float As[8][128];   // [k][m]
    __shared__ float Bs[8][128];   // [k][n]
    const int bm = blockIdx.y * 128, bn = blockIdx.x * 128;
    const int tid = threadIdx.x;
    const int ar = tid >> 1, ak = (tid & 1) * 4;       // A loader: row, k-quad
    const int bk = tid >> 5, bn4 = (tid & 31) * 4;     // B loader: k, n-quad
    const int ty = tid >> 4, tx = tid & 15;            // 16x16 compute layout

    // each 128-col block lies entirely in one branch half
    const float* Wp; const float* bp;
    if (bn < N_HID) { Wp = W1a + bn;            bp = b1a + bn; }
    else            { Wp = W1b + (bn - N_HID);  bp = b1b + (bn - N_HID); }

    float acc[8][8];
#pragma unroll
    for (int i = 0; i < 8; i++)
#pragma unroll
        for (int j = 0; j < 8; j++) acc[i][j] = 0.f;

    const int grow = bm + ar;
    for (int k0 = 0; k0 < N_FEAT; k0 += 8) {
        float4 av = make_float4(0.f, 0.f, 0.f, 0.f);
        if (grow < N_NODES && (k0 + ak) < N_FEAT)   // 500%4==0 -> quad all-valid or all-invalid
            av = *(const float4*)(x + (size_t)grow * N_FEAT + k0 + ak);
        As[ak + 0][ar] = av.x; As[ak + 1][ar] = av.y;
        As[ak + 2][ar] = av.z; As[ak + 3][ar] = av.w;

        float4 bv = make_float4(0.f, 0.f, 0.f, 0.f);
        if ((k0 + bk) < N_FEAT)
            bv = *(const float4*)(Wp + (size_t)(k0 + bk) * N_HID + bn4);
        *(float4*)&Bs[bk][bn4] = bv;
        __syncthreads();

#pragma unroll
        for (int kk = 0; kk < 8; kk++) {
            float a[8], b[8];
            *(float4*)&a[0] = *(const float4*)&As[kk][ty * 8];
            *(float4*)&a[4] = *(const float4*)&As[kk][ty * 8 + 4];
            *(float4*)&b[0] = *(const float4*)&Bs[kk][tx * 8];
            *(float4*)&b[4] = *(const float4*)&Bs[kk][tx * 8 + 4];
#pragma unroll
            for (int i = 0; i < 8; i++)
#pragma unroll
                for (int j = 0; j < 8; j++) acc[i][j] += a[i] * b[j];
        }
        __syncthreads();
    }

#pragma unroll
    for (int i = 0; i < 8; i++) {
        int r = bm + ty * 8 + i;
        if (r < N_NODES) {
#pragma unroll
            for (int j0 = 0; j0 < 8; j0 += 4) {
                int col = bn + tx * 8 + j0;
                float4 o;
                o.x = acc[i][j0 + 0] + bp[tx * 8 + j0 + 0];
                o.y = acc[i][j0 + 1] + bp[tx * 8 + j0 + 1];
                o.z = acc[i][j0 + 2] + bp[tx * 8 + j0 + 2];
                o.w = acc[i][j0 + 3] + bp[tx * 8 + j0 + 3];
                *(float4*)&g_y[(size_t)r * DCAT + col] = o;
            }
        }
    }
}

// ---------------- SpMM1: g[row] = relu( sum_e w * y[col] ), D=512 -------------
__global__ void __launch_bounds__(128) k_spmm1() {
    int row = blockIdx.x;
    int s = g_row_start[row], t = g_row_start[row + 1];
    int d = threadIdx.x * 4;
    float ax = 0.f, ay = 0.f, az = 0.f, aw = 0.f;
    for (int e = s; e < t; e++) {
        int   c = __ldg(&g_col[e]);
        float w = __ldg(&g_w[e]);
        float4 v = *(const float4*)&g_y[(size_t)c * DCAT + d];
        ax += w * v.x; ay += w * v.y; az += w * v.z; aw += w * v.w;
    }
    float4 o;
    o.x = fmaxf(ax, 0.f); o.y = fmaxf(ay, 0.f);
    o.z = fmaxf(az, 0.f); o.w = fmaxf(aw, 0.f);
    *(float4*)&g_g[(size_t)row * DCAT + d] = o;
}

// ---------------- GEMM2: z[row][0:10]=g1@W2_1+b2_1 ; z[row][10:20]=g2@W2_2+b2_2
__global__ void __launch_bounds__(256) k_gemm2(
    const float* __restrict__ W2a, const float* __restrict__ b2a,
    const float* __restrict__ W2b, const float* __restrict__ b2b)
{
    __shared__ float sW[DCAT * 10];   // [d][c], both halves concatenated
    for (int i = threadIdx.x; i < DCAT * 10; i += blockDim.x) {
        int d = i / 10, c = i % 10;
        sW[i] = (d < N_HID) ? W2a[d * 10 + c] : W2b[(d - N_HID) * 10 + c];
    }
    __syncthreads();

    int lane   = threadIdx.x & 31;
    int warp   = (blockIdx.x * blockDim.x + threadIdx.x) >> 5;
    int nwarps = (gridDim.x * blockDim.x) >> 5;

    for (int row = warp; row < N_NODES; row += nwarps) {
        float acc[20];
#pragma unroll
        for (int c = 0; c < 20; c++) acc[c] = 0.f;
        const float* grow = &g_g[(size_t)row * DCAT];
#pragma unroll
        for (int k = 0; k < 16; k++) {
            int d = lane + 32 * k;           // k<8 -> branch 1, k>=8 -> branch 2
            float gv = grow[d];
            const float* wrow = &sW[d * 10];
            float* ap = (k < 8) ? acc : acc + 10;
#pragma unroll
            for (int c = 0; c < 10; c++) ap[c] += gv * wrow[c];
        }
#pragma unroll
        for (int c = 0; c < 20; c++) {
            float v = acc[c];
            v += __shfl_xor_sync(0xffffffffu, v, 16);
            v += __shfl_xor_sync(0xffffffffu, v, 8);
            v += __shfl_xor_sync(0xffffffffu, v, 4);
            v += __shfl_xor_sync(0xffffffffu, v, 2);
            v += __shfl_xor_sync(0xffffffffu, v, 1);
            acc[c] = v;
        }
        if (lane == 0) {
#pragma unroll
            for (int c = 0; c < 10; c++) g_z[(size_t)row * 20 + c]      = acc[c]      + b2a[c];
#pragma unroll
            for (int c = 0; c < 10; c++) g_z[(size_t)row * 20 + 10 + c] = acc[10 + c] + b2b[c];
        }
    }
}

// ---------------- SpMM2: out[br][row][c] = sum_e w * z[col][br*10+c] ----------
__global__ void __launch_bounds__(256) k_spmm2(float* __restrict__ out) {
    int gt   = blockIdx.x * blockDim.x + threadIdx.x;
    int row  = gt >> 5;
    int lane = gt & 31;
    if (row >= N_NODES) return;
    if (lane < 20) {
        int s = g_row_start[row], t = g_row_start[row + 1];
        float acc = 0.f;
        for (int e = s; e < t; e++) {
            int   c = __ldg(&g_col[e]);
            float w = __ldg(&g_w[e]);
            acc += w * g_z[(size_t)c * 20 + lane];
        }
        int br = lane / 10, cc = lane % 10;
        out[(size_t)br * (N_NODES * N_CLASS) + (size_t)row * N_CLASS + cc] = acc;
    }
}

// ---------------- launch ------------------------------------------------------
extern "C" void kernel_launch(void* const* d_in, const int* in_sizes, int n_in,
                              void* d_out, int out_size)
{
    const float* x   = (const float*)d_in[0];
    const int*   ei  = (const int*)d_in[1];     // int32 view; width auto-detected
    const float* ew  = (const float*)d_in[2];
    const float* W1a = (const float*)d_in[3];
    const float* b1a = (const float*)d_in[4];
    const float* W2a = (const float*)d_in[5];
    const float* b2a = (const float*)d_in[6];
    const float* W1b = (const float*)d_in[7];
    const float* b1b = (const float*)d_in[8];
    const float* W2b = (const float*)d_in[9];
    const float* b2b = (const float*)d_in[10];
    float* out = (float*)d_out;

    k_detect<<<1, 32>>>(ei);
    k_zero<<<(N_NODES + 255) / 256, 256>>>();
    k_hist<<<(N_EDGES + 255) / 256, 256>>>(ei);
    k_scan<<<1, 1024>>>();
    k_scatter<<<(N_EDGES + 255) / 256, 256>>>(ei, ew);
    k_gemm1<<<dim3(DCAT / 128, (N_NODES + 127) / 128), 256>>>(x, W1a, b1a, W1b, b1b);
    k_spmm1<<<N_NODES, 128>>>();
    k_gemm2<<<782, 256>>>(W2a, b2a, W2b, b2b);
    k_spmm2<<<(N_NODES * 32 + 255) / 256, 256>>>(out);
}

// round 6
// speedup vs baseline: 1.7935x; 1.7935x over previous
#include <cuda_runtime.h>
#include <cuda_bf16.h>

#define N_NODES 50000
#define N_EDGES 800000
#define N_FEAT  500
#define N_HID   256
#define DCAT    512   // fused hidden width (2 branches x 256)
#define N_CLASS 10
#define MPAD    50048 // 391 * 128, padded row count for GEMM1
#define KPAD    512   // padded K for GEMM1

// ---------------- device scratch (static; no allocations allowed) -------------
__device__ int   g_is64;
__device__ int   g_counts[N_NODES];
__device__ int   g_row_start[N_NODES + 1];
__device__ int   g_cursor[N_NODES];
__device__ int   g_blockSums[256];
__device__ int   g_blockOffs[256];
__device__ int   g_col[N_EDGES];
__device__ float g_w[N_EDGES];
__device__ __align__(16) __nv_bfloat16 g_xh[(size_t)MPAD * KPAD];
__device__ __align__(16) __nv_bfloat16 g_xl[(size_t)MPAD * KPAD];
__device__ __align__(16) __nv_bfloat16 g_whT[DCAT * KPAD];  // [n][k]
__device__ __align__(16) __nv_bfloat16 g_wlT[DCAT * KPAD];  // [n][k]
__device__ float g_bcat[DCAT];
__device__ __align__(16) float g_y[(size_t)MPAD * DCAT];    // x@W1cat + b1cat
__device__ __align__(16) float g_g[(size_t)N_NODES * DCAT]; // relu(spmm(y))
__device__ float g_z[(size_t)N_NODES * 20];

// ---------------- dtype detect ------------------------------------------------
__global__ void k_detect(const int* __restrict__ ei32) {
    if (threadIdx.x == 0) {
        int odd_nonzero = 0;
        for (int i = 0; i < 64; i++) odd_nonzero |= ei32[2 * i + 1];
        g_is64 = (odd_nonzero == 0) ? 1 : 0;
    }
}
__device__ __forceinline__ int edge_row(const int* ei32, int e, int is64) {
    return is64 ? ei32[2 * e] : ei32[e];
}
__device__ __forceinline__ int edge_col(const int* ei32, int e, int is64) {
    return is64 ? ei32[2 * (N_EDGES + e)] : ei32[N_EDGES + e];
}

// ---------------- CSR build ---------------------------------------------------
__global__ void k_zero() {
    int i = blockIdx.x * blockDim.x + threadIdx.x;
    if (i < N_NODES) { g_counts[i] = 0; g_cursor[i] = 0; }
}

__global__ void k_hist(const int* __restrict__ ei32) {
    int e = blockIdx.x * blockDim.x + threadIdx.x;
    if (e < N_EDGES) {
        int r = edge_row(ei32, e, g_is64);
        if ((unsigned)r < N_NODES) atomicAdd(&g_counts[r], 1);
    }
}

// parallel scan: (1) per-block reduce, (2) scan block sums, (3) block scan + offset
__global__ void k_scan1() {
    __shared__ int sm[256];
    int i = blockIdx.x * 256 + threadIdx.x;
    sm[threadIdx.x] = (i < N_NODES) ? g_counts[i] : 0;
    __syncthreads();
    for (int off = 128; off; off >>= 1) {
        if (threadIdx.x < off) sm[threadIdx.x] += sm[threadIdx.x + off];
        __syncthreads();
    }
    if (threadIdx.x == 0) g_blockSums[blockIdx.x] = sm[0];
}

__global__ void k_scan2(int nblocks) {
    __shared__ int sm[256];
    int v = (threadIdx.x < nblocks) ? g_blockSums[threadIdx.x] : 0;
    sm[threadIdx.x] = v;
    __syncthreads();
    for (int off = 1; off < 256; off <<= 1) {
        int t = (threadIdx.x >= off) ? sm[threadIdx.x - off] : 0;
        __syncthreads();
        sm[threadIdx.x] += t;
        __syncthreads();
    }
    if (threadIdx.x < nblocks) g_blockOffs[threadIdx.x] = sm[threadIdx.x] - v;
    if (threadIdx.x == 255) g_row_start[N_NODES] = sm[255];
}

__global__ void k_scan3() {
    __shared__ int sm[256];
    int i = blockIdx.x * 256 + threadIdx.x;
    int v = (i < N_NODES) ? g_counts[i] : 0;
    sm[threadIdx.x] = v;
    __syncthreads();
    for (int off = 1; off < 256; off <<= 1) {
        int t = (threadIdx.x >= off) ? sm[threadIdx.x - off] : 0;
        __syncthreads();
        sm[threadIdx.x] += t;
        __syncthreads();
    }
    if (i < N_NODES) g_row_start[i] = g_blockOffs[blockIdx.x] + sm[threadIdx.x] - v;
}

__global__ void k_scatter(const int* __restrict__ ei32,
                          const float* __restrict__ ew) {
    int e = blockIdx.x * blockDim.x + threadIdx.x;
    if (e < N_EDGES) {
        int is64 = g_is64;
        int r = edge_row(ei32, e, is64);
        int c = edge_col(ei32, e, is64);
        if ((unsigned)r < N_NODES && (unsigned)c < N_NODES) {
            int p = g_row_start[r] + atomicAdd(&g_cursor[r], 1);
            g_col[p] = c;
            g_w[p]   = ew[e];
        }
    }
}

// ---------------- split-precision prep ----------------------------------------
__global__ void k_prep_x(const float* __restrict__ x) {
    int t  = blockIdx.x * 256 + threadIdx.x;
    int r  = t >> 7;
    int c0 = (t & 127) * 4;
    if (r >= MPAD) return;
    float4 v = make_float4(0.f, 0.f, 0.f, 0.f);
    if (r < N_NODES && c0 < N_FEAT)
        v = *(const float4*)(x + (size_t)r * N_FEAT + c0);
    float vv[4] = {v.x, v.y, v.z, v.w};
    __nv_bfloat16 h[4], l[4];
#pragma unroll
    for (int i = 0; i < 4; i++) {
        h[i] = __float2bfloat16(vv[i]);
        l[i] = __float2bfloat16(vv[i] - __bfloat162float(h[i]));
    }
    *(uint2*)(g_xh + (size_t)r * KPAD + c0) = *(uint2*)h;
    *(uint2*)(g_xl + (size_t)r * KPAD + c0) = *(uint2*)l;
}

__global__ void k_prep_w(const float* __restrict__ W1a, const float* __restrict__ b1a,
                         const float* __restrict__ W1b, const float* __restrict__ b1b) {
    int t = blockIdx.x * 256 + threadIdx.x;  // over DCAT*KPAD
    if (t >= DCAT * KPAD) return;
    int n = t >> 9, k = t & 511;
    float v = 0.f;
    if (k < N_FEAT)
        v = (n < N_HID) ? W1a[k * N_HID + n] : W1b[k * N_HID + (n - N_HID)];
    __nv_bfloat16 h = __float2bfloat16(v);
    g_whT[n * KPAD + k] = h;
    g_wlT[n * KPAD + k] = __float2bfloat16(v - __bfloat162float(h));
    if (t < DCAT) g_bcat[t] = (t < N_HID) ? b1a[t] : b1b[t - N_HID];
}

// ---------------- GEMM1 (tensor cores, bf16 split precision) ------------------
#define BM 128
#define BN 128
#define BK 16
#define PITCH 24  // bf16 elements per smem row (48B: 16B-aligned, conflict-free frags)

__device__ __forceinline__ void mma16816(float* c, const unsigned* a, const unsigned* b) {
    asm volatile(
        "mma.sync.aligned.m16n8k16.row.col.f32.bf16.bf16.f32 "
        "{%0,%1,%2,%3}, {%4,%5,%6,%7}, {%8,%9}, {%0,%1,%2,%3};\n"
        : "+f"(c[0]), "+f"(c[1]), "+f"(c[2]), "+f"(c[3])
        : "r"(a[0]), "r"(a[1]), "r"(a[2]), "r"(a[3]), "r"(b[0]), "r"(b[1]));
}

__global__ void __launch_bounds__(256) k_gemm1_mma() {
    __shared__ __align__(16) __nv_bfloat16 sAh[2][BM * PITCH];
    __shared__ __align__(16) __nv_bfloat16 sAl[2][BM * PITCH];
    __shared__ __align__(16) __nv_bfloat16 sBh[2][BN * PITCH];
    __shared__ __align__(16) __nv_bfloat16 sBl[2][BN * PITCH];

    const int tid  = threadIdx.x;
    const int bm   = blockIdx.y * BM;
    const int bn   = blockIdx.x * BN;
    const int wid  = tid >> 5, lane = tid & 31;
    const int wm   = wid & 1, wn = wid >> 1;   // 2x4 warps -> 64x32 warp tiles
    const int mw   = wm * 64, nw = wn * 32;
    const int gid  = lane >> 2;                // 0..7
    const int tk4  = lane & 3;                 // 0..3

    // gmem->smem loader mapping: 256 threads, each one uint4 (8 bf16) per matrix
    const int lr = tid >> 1;
    const int lk = (tid & 1) * 8;
    const size_t aoff = (size_t)(bm + lr) * KPAD + lk;
    const size_t boff = (size_t)(bn + lr) * KPAD + lk;
    const int soff = lr * PITCH + lk;

    float acc[16][4];
#pragma unroll
    for (int i = 0; i < 16; i++)
#pragma unroll
        for (int j = 0; j < 4; j++) acc[i][j] = 0.f;

    // prologue: stage 0
    {
        *(uint4*)&sAh[0][soff] = *(const uint4*)(g_xh + aoff);
        *(uint4*)&sAl[0][soff] = *(const uint4*)(g_xl + aoff);
        *(uint4*)&sBh[0][soff] = *(const uint4*)(g_whT + boff);
        *(uint4*)&sBl[0][soff] = *(const uint4*)(g_wlT + boff);
    }
    __syncthreads();

    const int NSTAGE = KPAD / BK;  // 32
    for (int s = 0; s < NSTAGE; s++) {
        const int cur = s & 1, nxt = cur ^ 1;
        uint4 pAh, pAl, pBh, pBl;
        if (s + 1 < NSTAGE) {
            int k0 = (s + 1) * BK;
            pAh = *(const uint4*)(g_xh + aoff + k0);
            pAl = *(const uint4*)(g_xl + aoff + k0);
            pBh = *(const uint4*)(g_whT + boff + k0);
            pBl = *(const uint4*)(g_wlT + boff + k0);
        }

        // fragment loads
        unsigned Ah[4][4], Al[4][4], Bh[4][2], Bl[4][2];
#pragma unroll
        for (int ni = 0; ni < 4; ni++) {
            int n = nw + ni * 8 + gid;
            Bh[ni][0] = *(const unsigned*)&sBh[cur][n * PITCH + tk4 * 2];
            Bh[ni][1] = *(const unsigned*)&sBh[cur][n * PITCH + tk4 * 2 + 8];
            Bl[ni][0] = *(const unsigned*)&sBl[cur][n * PITCH + tk4 * 2];
            Bl[ni][1] = *(const unsigned*)&sBl[cur][n * PITCH + tk4 * 2 + 8];
        }
#pragma unroll
        for (int mi = 0; mi < 4; mi++) {
            int m = mw + mi * 16 + gid;
            Ah[mi][0] = *(const unsigned*)&sAh[cur][m * PITCH + tk4 * 2];
            Ah[mi][1] = *(const unsigned*)&sAh[cur][(m + 8) * PITCH + tk4 * 2];
            Ah[mi][2] = *(const unsigned*)&sAh[cur][m * PITCH + tk4 * 2 + 8];
            Ah[mi][3] = *(const unsigned*)&sAh[cur][(m + 8) * PITCH + tk4 * 2 + 8];
            Al[mi][0] = *(const unsigned*)&sAl[cur][m * PITCH + tk4 * 2];
            Al[mi][1] = *(const unsigned*)&sAl[cur][(m + 8) * PITCH + tk4 * 2];
            Al[mi][2] = *(const unsigned*)&sAl[cur][m * PITCH + tk4 * 2 + 8];
            Al[mi][3] = *(const unsigned*)&sAl[cur][(m + 8) * PITCH + tk4 * 2 + 8];
        }
#pragma unroll
        for (int mi = 0; mi < 4; mi++)
#pragma unroll
            for (int ni = 0; ni < 4; ni++) {
                mma16816(acc[mi * 4 + ni], Ah[mi], Bh[ni]);
                mma16816(acc[mi * 4 + ni], Ah[mi], Bl[ni]);
                mma16816(acc[mi * 4 + ni], Al[mi], Bh[ni]);
            }

        if (s + 1 < NSTAGE) {
            *(uint4*)&sAh[nxt][soff] = pAh;
            *(uint4*)&sAl[nxt][soff] = pAl;
            *(uint4*)&sBh[nxt][soff] = pBh;
            *(uint4*)&sBl[nxt][soff] = pBl;
        }
        __syncthreads();
    }

    // epilogue: add bias, store fp32 (rows padded -> no guard)
#pragma unroll
    for (int mi = 0; mi < 4; mi++) {
#pragma unroll
        for (int ni = 0; ni < 4; ni++) {
            int r = bm + mw + mi * 16 + gid;
            int c = bn + nw + ni * 8 + tk4 * 2;
            float b0 = g_bcat[c], b1 = g_bcat[c + 1];
            float* acc4 = acc[mi * 4 + ni];
            float2 v0 = make_float2(acc4[0] + b0, acc4[1] + b1);
            float2 v1 = make_float2(acc4[2] + b0, acc4[3] + b1);
            *(float2*)&g_y[(size_t)r * DCAT + c] = v0;
            *(float2*)&g_y[(size_t)(r + 8) * DCAT + c] = v1;
        }
    }
}

// ---------------- SpMM1: g[row] = relu( sum_e w * y[col] ), D=512 -------------
__global__ void __launch_bounds__(128) k_spmm1() {
    int row = blockIdx.x;
    int s = g_row_start[row], t = g_row_start[row + 1];
    int d = threadIdx.x * 4;
    float ax = 0.f, ay = 0.f, az = 0.f, aw = 0.f;
    for (int e = s; e < t; e++) {
        int   c = __ldg(&g_col[e]);
        float w = __ldg(&g_w[e]);
        float4 v = *(const float4*)&g_y[(size_t)c * DCAT + d];
        ax += w * v.x; ay += w * v.y; az += w * v.z; aw += w * v.w;
    }
    float4 o;
    o.x = fmaxf(ax, 0.f); o.y = fmaxf(ay, 0.f);
    o.z = fmaxf(az, 0.f); o.w = fmaxf(aw, 0.f);
    *(float4*)&g_g[(size_t)row * DCAT + d] = o;
}

// ---------------- GEMM2 -------------------------------------------------------
__global__ void __launch_bounds__(256) k_gemm2(
    const float* __restrict__ W2a, const float* __restrict__ b2a,
    const float* __restrict__ W2b, const float* __restrict__ b2b)
{
    __shared__ float sW[DCAT * 10];
    for (int i = threadIdx.x; i < DCAT * 10; i += blockDim.x) {
        int d = i / 10, c = i % 10;
        sW[i] = (d < N_HID) ? W2a[d * 10 + c] : W2b[(d - N_HID) * 10 + c];
    }
    __syncthreads();

    int lane   = threadIdx.x & 31;
    int warp   = (blockIdx.x * blockDim.x + threadIdx.x) >> 5;
    int nwarps = (gridDim.x * blockDim.x) >> 5;

    for (int row = warp; row < N_NODES; row += nwarps) {
        float acc[20];
#pragma unroll
        for (int c = 0; c < 20; c++) acc[c] = 0.f;
        const float* grow = &g_g[(size_t)row * DCAT];
#pragma unroll
        for (int k = 0; k < 16; k++) {
            int d = lane + 32 * k;
            float gv = grow[d];
            const float* wrow = &sW[d * 10];
            float* ap = (k < 8) ? acc : acc + 10;
#pragma unroll
            for (int c = 0; c < 10; c++) ap[c] += gv * wrow[c];
        }
#pragma unroll
        for (int c = 0; c < 20; c++) {
            float v = acc[c];
            v += __shfl_xor_sync(0xffffffffu, v, 16);
            v += __shfl_xor_sync(0xffffffffu, v, 8);
            v += __shfl_xor_sync(0xffffffffu, v, 4);
            v += __shfl_xor_sync(0xffffffffu, v, 2);
            v += __shfl_xor_sync(0xffffffffu, v, 1);
            acc[c] = v;
        }
        if (lane == 0) {
#pragma unroll
            for (int c = 0; c < 10; c++) g_z[(size_t)row * 20 + c]      = acc[c]      + b2a[c];
#pragma unroll
            for (int c = 0; c < 10; c++) g_z[(size_t)row * 20 + 10 + c] = acc[10 + c] + b2b[c];
        }
    }
}

// ---------------- SpMM2 -------------------------------------------------------
__global__ void __launch_bounds__(256) k_spmm2(float* __restrict__ out) {
    int gt   = blockIdx.x * blockDim.x + threadIdx.x;
    int row  = gt >> 5;
    int lane = gt & 31;
    if (row >= N_NODES) return;
    if (lane < 20) {
        int s = g_row_start[row], t = g_row_start[row + 1];
        float acc = 0.f;
        for (int e = s; e < t; e++) {
            int   c = __ldg(&g_col[e]);
            float w = __ldg(&g_w[e]);
            acc += w * g_z[(size_t)c * 20 + lane];
        }
        int br = lane / 10, cc = lane % 10;
        out[(size_t)br * (N_NODES * N_CLASS) + (size_t)row * N_CLASS + cc] = acc;
    }
}

// ---------------- launch ------------------------------------------------------
extern "C" void kernel_launch(void* const* d_in, const int* in_sizes, int n_in,
                              void* d_out, int out_size)
{
    const float* x   = (const float*)d_in[0];
    const int*   ei  = (const int*)d_in[1];
    const float* ew  = (const float*)d_in[2];
    const float* W1a = (const float*)d_in[3];
    const float* b1a = (const float*)d_in[4];
    const float* W2a = (const float*)d_in[5];
    const float* b2a = (const float*)d_in[6];
    const float* W1b = (const float*)d_in[7];
    const float* b1b = (const float*)d_in[8];
    const float* W2b = (const float*)d_in[9];
    const float* b2b = (const float*)d_in[10];
    float* out = (float*)d_out;

    const int SCAN_BLOCKS = (N_NODES + 255) / 256;  // 196

    k_detect<<<1, 32>>>(ei);
    k_zero<<<(N_NODES + 255) / 256, 256>>>();
    k_hist<<<(N_EDGES + 255) / 256, 256>>>(ei);
    k_scan1<<<SCAN_BLOCKS, 256>>>();
    k_scan2<<<1, 256>>>(SCAN_BLOCKS);
    k_scan3<<<SCAN_BLOCKS, 256>>>();
    k_scatter<<<(N_EDGES + 255) / 256, 256>>>(ei, ew);
    k_prep_x<<<(MPAD * 128 + 255) / 256, 256>>>(x);
    k_prep_w<<<(DCAT * KPAD + 255) / 256, 256>>>(W1a, b1a, W1b, b1b);
    k_gemm1_mma<<<dim3(DCAT / BN, MPAD / BM), 256>>>();
    k_spmm1<<<N_NODES, 128>>>();
    k_gemm2<<<782, 256>>>(W2a, b2a, W2b, b2b);
    k_spmm2<<<(N_NODES * 32 + 255) / 256, 256>>>(out);
}